// round 15
// baseline (speedup 1.0000x reference)
#include <cuda_runtime.h>
#include <cuda_fp16.h>
#include <cstdint>

// out[32,14336] = (x * scales) @ W^T
//   x: [32,4096] f32, W: [14336,4096] int32 (|w|<=127), scales: [4096] f32
// HBM-bound: 235MB weight stream -> floor ~29.4us.
// R14: W streamed via cp.async.bulk (TMA-class engine) + mbarrier ring.
// Every LDG-based variant plateaued at 66-72% DRAM; model says the per-lane
// MSHR/outstanding-request pool saturates before HBM does. Bulk copies move
// 512B/request through the async engine with no per-lane MSHRs. 3-deep ring,
// stage = 32 rows x 512B @ 576B pitch (conflict-free LDS.128, R11 geometry).
// A-frags stay direct LDG (L2-resident). PDL overlap retained.

#define TOKENS 32
#define IN_F   4096
#define OUT_F  14336
#define NUM_KB (IN_F / 16)        // 256 k16-blocks
#define NWARPS 8
#define NSTAGES 32                // stage s covers k-ints [s*128, s*128+128)

#define PITCH 576                  // smem row pitch: 512B data + 64B pad
#define STAGE_BYTES (32 * PITCH)   // 18432 B
#define NBUF 3
#define SMEM_DATA (NBUF * STAGE_BYTES)      // 55296 B
#define SMEM_TOTAL (SMEM_DATA + 128)        // + mbarriers

// A-fragments of xs=x*scales in fp16, fragment-major (permuted k-layout):
// index ((kb*2 + mi)*32 + lane) -> uint4 (8 fp16 = one m16k16 A frag slice)
__device__ uint4 g_xsfrag[NUM_KB * 2 * 32];

// ---------------------------------------------------------------------------
// Prep: build fragment-major fp16 xs with the permuted k-layout.
// lane quad q owns physical k = kb*16 + 4q .. 4q+3 (one contiguous float4).
// ---------------------------------------------------------------------------
__global__ __launch_bounds__(256) void prep_xs_kernel(
    const float* __restrict__ x, const float* __restrict__ scales)
{
    int wg   = blockIdx.x * (blockDim.x >> 5) + (threadIdx.x >> 5); // 0..511
    int lane = threadIdx.x & 31;
    int kb = wg >> 1;
    int mi = wg & 1;

    int q = lane & 3;
    int g = lane >> 2;
    int r0 = mi * 16 + g;
    int r1 = r0 + 8;
    int k0 = kb * 16 + 4 * q;

    float4 s  = *(const float4*)(scales + k0);
    float4 x0 = *(const float4*)(x + r0 * IN_F + k0);
    float4 x1 = *(const float4*)(x + r1 * IN_F + k0);

    __half2 h0 = __floats2half2_rn(x0.x * s.x, x0.y * s.y);
    __half2 h1 = __floats2half2_rn(x1.x * s.x, x1.y * s.y);
    __half2 h2 = __floats2half2_rn(x0.z * s.z, x0.w * s.w);
    __half2 h3 = __floats2half2_rn(x1.z * s.z, x1.w * s.w);

    uint4 v;
    v.x = *(const uint32_t*)&h0;
    v.y = *(const uint32_t*)&h1;
    v.z = *(const uint32_t*)&h2;
    v.w = *(const uint32_t*)&h3;
    g_xsfrag[(kb * 2 + mi) * 32 + lane] = v;

    asm volatile("griddepcontrol.launch_dependents;");
}

// ---------------------------------------------------------------------------
__device__ __forceinline__ void mma16816(float c[4],
    uint32_t a0, uint32_t a1, uint32_t a2, uint32_t a3,
    uint32_t b0, uint32_t b1)
{
    asm volatile(
        "mma.sync.aligned.m16n8k16.row.col.f32.f16.f16.f32 "
        "{%0,%1,%2,%3}, {%4,%5,%6,%7}, {%8,%9}, {%0,%1,%2,%3};\n"
        : "+f"(c[0]), "+f"(c[1]), "+f"(c[2]), "+f"(c[3])
        : "r"(a0), "r"(a1), "r"(a2), "r"(a3), "r"(b0), "r"(b1));
}

__device__ __forceinline__ uint32_t pack_w_h2(int w0, int w1)
{
    __half2 h = __halves2half2(__int2half_rn(w0), __int2half_rn(w1));
    return *(const uint32_t*)&h;
}

__device__ __forceinline__ void bulk_cp512(uint32_t dst, const void* src,
                                           uint32_t mbar)
{
    asm volatile(
        "cp.async.bulk.shared::cta.global.mbarrier::complete_tx::bytes "
        "[%0], [%1], 512, [%2];\n"
        :: "r"(dst), "l"(src), "r"(mbar) : "memory");
}

__device__ __forceinline__ void mbar_init(uint32_t mbar, uint32_t count)
{
    asm volatile("mbarrier.init.shared.b64 [%0], %1;\n"
                 :: "r"(mbar), "r"(count) : "memory");
}
__device__ __forceinline__ void mbar_expect_tx(uint32_t mbar, uint32_t bytes)
{
    asm volatile("mbarrier.arrive.expect_tx.shared.b64 _, [%0], %1;\n"
                 :: "r"(mbar), "r"(bytes) : "memory");
}
__device__ __forceinline__ void mbar_arrive(uint32_t mbar)
{
    asm volatile("mbarrier.arrive.shared.b64 _, [%0];\n"
                 :: "r"(mbar) : "memory");
}
__device__ __forceinline__ void mbar_wait(uint32_t mbar, uint32_t parity)
{
    asm volatile(
        "{\n\t.reg .pred P;\n"
        "WAIT_%=:\n\t"
        "mbarrier.try_wait.parity.acquire.cta.shared::cta.b64 P, [%0], %1, 0x989680;\n\t"
        "@P bra.uni DONE_%=;\n\t"
        "bra.uni WAIT_%=;\n"
        "DONE_%=:\n\t}"
        :: "r"(mbar), "r"(parity) : "memory");
}

// ---------------------------------------------------------------------------
// GEMM: 448 CTAs x 256 threads, occ 3. CTA = 32 output rows x full K.
// Warp w consumes kb = s*8 + w from stage s (col bytes w*64+q*16, rows g+8j).
// ---------------------------------------------------------------------------
__global__ void __launch_bounds__(256, 3) gemm_q8_kernel(
    const int* __restrict__ W, float* __restrict__ out)
{
    extern __shared__ char smem_raw[];
    const uint32_t smem_base = (uint32_t)__cvta_generic_to_shared(smem_raw);
    const uint32_t mb_full  = smem_base + SMEM_DATA;        // 3 x 8B
    const uint32_t mb_empty = smem_base + SMEM_DATA + 24;   // 3 x 8B

    const int tid  = threadIdx.x;
    const int lane = tid & 31;
    const int warp = tid >> 5;
    const int n0   = blockIdx.x * 32;

    const int q = lane & 3;
    const int g = lane >> 2;

    // init barriers
    if (tid == 0) {
        #pragma unroll
        for (int b = 0; b < NBUF; b++) {
            mbar_init(mb_full  + b * 8, 1);    // producer's expect_tx arrive
            mbar_init(mb_empty + b * 8, 256);  // all threads arrive
        }
    }
    __syncthreads();

    const int* wbase = W + (size_t)n0 * IN_F;   // CTA's 32-row slab

    // ---- prologue: produce stages 0,1 (no empty wait; buffers fresh) ----
    if (tid == 0) {
        #pragma unroll
        for (int s = 0; s < 2; s++) {
            const uint32_t mbar = mb_full + s * 8;
            mbar_expect_tx(mbar, 32 * 512);
            uint32_t dst = smem_base + s * STAGE_BYTES;
            const int* src = wbase + s * 128;
            #pragma unroll 4
            for (int r = 0; r < 32; r++)
                bulk_cp512(dst + r * PITCH, src + (size_t)r * IN_F, mbar);
        }
    }

    // wait for prep's A-fragment stores (PDL)
    asm volatile("griddepcontrol.wait;" ::: "memory");

    // accumulators
    float c[2][4][4];
    #pragma unroll
    for (int a = 0; a < 2; a++)
        #pragma unroll
        for (int b = 0; b < 4; b++)
            #pragma unroll
            for (int d = 0; d < 4; d++) c[a][b][d] = 0.0f;

    // fragment read base: row g (+8j), col warp*64 + q*16
    const uint32_t frag_base = smem_base + g * PITCH + warp * 64 + q * 16;

    for (int s = 0; s < NSTAGES; s++) {
        const int b = s % NBUF;

        // producer: refill stage s+2 into buffer (s+2)%NBUF
        if (tid == 0 && s + 2 < NSTAGES) {
            const int sp = s + 2;
            const int bp = sp % NBUF;
            const int n  = sp / NBUF;
            if (n >= 1) mbar_wait(mb_empty + bp * 8, (n - 1) & 1);
            const uint32_t mbar = mb_full + bp * 8;
            mbar_expect_tx(mbar, 32 * 512);
            uint32_t dst = smem_base + bp * STAGE_BYTES;
            const int* src = wbase + sp * 128;
            #pragma unroll 4
            for (int r = 0; r < 32; r++)
                bulk_cp512(dst + r * PITCH, src + (size_t)r * IN_F, mbar);
        }

        // A fragments for this stage (issue before the wait; latency hides)
        const int kb = s * 8 + warp;
        uint4 A0 = g_xsfrag[(kb * 2 + 0) * 32 + lane];
        uint4 A1 = g_xsfrag[(kb * 2 + 1) * 32 + lane];

        // wait for stage s data
        mbar_wait(mb_full + b * 8, (s / NBUF) & 1);

        // compute: 4 LDS.128 + 8 MMAs
        const uint32_t buf = frag_base + b * STAGE_BYTES;
        #pragma unroll
        for (int j = 0; j < 4; j++) {
            int4 wv;
            asm volatile("ld.shared.v4.b32 {%0,%1,%2,%3}, [%4];\n"
                         : "=r"(wv.x), "=r"(wv.y), "=r"(wv.z), "=r"(wv.w)
                         : "r"(buf + j * (8 * PITCH)));
            uint32_t b0 = pack_w_h2(wv.x, wv.y);
            uint32_t b1 = pack_w_h2(wv.z, wv.w);
            mma16816(c[0][j], A0.x, A0.y, A0.z, A0.w, b0, b1);
            mma16816(c[1][j], A1.x, A1.y, A1.z, A1.w, b0, b1);
        }

        // release buffer
        mbar_arrive(mb_empty + b * 8);
    }

    // ---- cross-warp K reduction: overlay red on the staging smem ----
    __syncthreads();
    float (*red)[TOKENS][32] = (float (*)[TOKENS][32])smem_raw;
    #pragma unroll
    for (int mi = 0; mi < 2; mi++) {
        #pragma unroll
        for (int j = 0; j < 4; j++) {
            int row = mi * 16 + g;
            int col = j * 8 + 2 * q;
            *(float2*)&red[warp][row][col]     = make_float2(c[mi][j][0], c[mi][j][1]);
            *(float2*)&red[warp][row + 8][col] = make_float2(c[mi][j][2], c[mi][j][3]);
        }
    }
    __syncthreads();

    const int col   = tid & 31;
    const int rbase = (tid >> 5) * 4;
    #pragma unroll
    for (int i = 0; i < 4; i++) {
        int row = rbase + i;
        float v = 0.0f;
        #pragma unroll
        for (int w = 0; w < NWARPS; w++) v += red[w][row][col];
        out[(size_t)row * OUT_F + n0 + col] = v;
    }
}

// ---------------------------------------------------------------------------
extern "C" void kernel_launch(void* const* d_in, const int* in_sizes, int n_in,
                              void* d_out, int out_size)
{
    const float* x      = (const float*)d_in[0];
    const int*   weight = (const int*)d_in[1];
    const float* scales = (const float*)d_in[2];
    float*       out    = (float*)d_out;

    cudaFuncSetAttribute(gemm_q8_kernel,
                         cudaFuncAttributeMaxDynamicSharedMemorySize, SMEM_TOTAL);

    prep_xs_kernel<<<64, 256>>>(x, scales);

    cudaLaunchConfig_t cfg = {};
    cfg.gridDim  = dim3(OUT_F / 32, 1, 1);
    cfg.blockDim = dim3(256, 1, 1);
    cfg.dynamicSmemBytes = SMEM_TOTAL;
    cfg.stream = 0;
    cudaLaunchAttribute attr[1];
    attr[0].id = cudaLaunchAttributeProgrammaticStreamSerialization;
    attr[0].val.programmaticStreamSerializationAllowed = 1;
    cfg.attrs = attr;
    cfg.numAttrs = 1;
    cudaLaunchKernelEx(&cfg, gemm_q8_kernel, weight, out);
}